// round 1
// baseline (speedup 1.0000x reference)
#include <cuda_runtime.h>
#include <cstdint>

#define DHID 128
#define KNB 32
#define SA_STRIDE 132   // 128 + 4 pad: conflict-free mma fragment LDS

// Scratch for x_s = x @ Wx^T + bx  (device global: allocation rules forbid cudaMalloc)
__device__ float g_xs[65536 * 128];

__device__ __forceinline__ uint32_t f2tf32(float f) {
    uint32_t r;
    asm volatile("cvt.rna.tf32.f32 %0, %1;" : "=r"(r) : "f"(f));
    return r;
}

__device__ __forceinline__ void mma_tf32(float c[4], const uint32_t a[4], const uint32_t b[2]) {
    asm volatile(
        "mma.sync.aligned.m16n8k8.row.col.f32.tf32.tf32.f32 "
        "{%0,%1,%2,%3}, {%4,%5,%6,%7}, {%8,%9}, {%0,%1,%2,%3};"
        : "+f"(c[0]), "+f"(c[1]), "+f"(c[2]), "+f"(c[3])
        : "r"(a[0]), "r"(a[1]), "r"(a[2]), "r"(a[3]), "r"(b[0]), "r"(b[1]));
}

// ---------------------------------------------------------------------------
// Kernel 1: x_s[n,d] = sum_e x[n,e] * Wx[d,e] + bx[d]   -> g_xs
// One CTA = 128 rows. 256 threads, 8 warps tiled 4(M=32) x 2(N=64).
// ---------------------------------------------------------------------------
__global__ __launch_bounds__(256) void xs_kernel(
    const float* __restrict__ x, const float* __restrict__ Wx,
    const float* __restrict__ bx, int N)
{
    extern __shared__ float smem[];
    float* sW  = smem;                      // 128*132 (tf32 bit patterns)
    float* sA  = sW + 128 * SA_STRIDE;      // 128*132 (tf32 bit patterns)
    float* sbx = sA + 128 * SA_STRIDE;      // 128

    const int tid = threadIdx.x;
    const int tileBase = blockIdx.x * 128;

    for (int i = tid; i < 128 * 128; i += 256) {
        int d = i >> 7, e = i & 127;
        ((uint32_t*)sW)[d * SA_STRIDE + e] = f2tf32(Wx[i]);
    }
    for (int i = tid; i < 128 * 128; i += 256) {
        int r = i >> 7, e = i & 127;
        int node = tileBase + r;
        float v = (node < N) ? x[node * 128 + e] : 0.f;
        ((uint32_t*)sA)[r * SA_STRIDE + e] = f2tf32(v);
    }
    if (tid < 128) sbx[tid] = bx[tid];
    __syncthreads();

    const int w = tid >> 5, lane = tid & 31;
    const int lg = lane >> 2, lc = lane & 3;
    const int wm = w >> 1, wn = w & 1;

    float acc[2][8][4];
#pragma unroll
    for (int mi = 0; mi < 2; mi++)
#pragma unroll
        for (int ni = 0; ni < 8; ni++)
#pragma unroll
            for (int j = 0; j < 4; j++) acc[mi][ni][j] = 0.f;

    const uint32_t* uA = (const uint32_t*)sA;
    const uint32_t* uW = (const uint32_t*)sW;

#pragma unroll 4
    for (int ks = 0; ks < 16; ks++) {
        const int e0 = ks * 8;
        uint32_t afr[2][4];
#pragma unroll
        for (int mi = 0; mi < 2; mi++) {
            int r = wm * 32 + mi * 16 + lg;
            afr[mi][0] = uA[r * SA_STRIDE + e0 + lc];
            afr[mi][1] = uA[(r + 8) * SA_STRIDE + e0 + lc];
            afr[mi][2] = uA[r * SA_STRIDE + e0 + 4 + lc];
            afr[mi][3] = uA[(r + 8) * SA_STRIDE + e0 + 4 + lc];
        }
#pragma unroll
        for (int ni = 0; ni < 8; ni++) {
            int c0 = wn * 64 + ni * 8;
            uint32_t bfr[2];
            bfr[0] = uW[(c0 + lg) * SA_STRIDE + e0 + lc];
            bfr[1] = uW[(c0 + lg) * SA_STRIDE + e0 + 4 + lc];
            mma_tf32(acc[0][ni], afr[0], bfr);
            mma_tf32(acc[1][ni], afr[1], bfr);
        }
    }

#pragma unroll
    for (int mi = 0; mi < 2; mi++) {
#pragma unroll
        for (int rh = 0; rh < 2; rh++) {
            int r = wm * 32 + mi * 16 + rh * 8 + lg;
            int node = tileBase + r;
            if (node < N) {
#pragma unroll
                for (int ni = 0; ni < 8; ni++) {
#pragma unroll
                    for (int cc = 0; cc < 2; cc++) {
                        int d = wn * 64 + ni * 8 + 2 * lc + cc;
                        g_xs[node * 128 + d] = acc[mi][ni][rh * 2 + cc] + sbx[d];
                    }
                }
            }
        }
    }
}

// ---------------------------------------------------------------------------
// Main kernel (persistent): per tile of 2 nodes:
//   n_s = x_nb_tile[64,128] @ Wn^T  (tf32 mma, Wn resident in smem)
//   h   = n_s + x_s + bn + bw + weight*Ww ; leaky(0.1) ; score = h . Wl
//   softmax over K=32 ; out = attn @ x_nb_tile (from smem)
// 256 threads = 8 warps tiled 4(M=16) x 2(N=64).
// ---------------------------------------------------------------------------
__global__ __launch_bounds__(256) void gnn_main_kernel(
    const float* __restrict__ x_nb, const float* __restrict__ weight,
    const float* __restrict__ Wn, const float* __restrict__ bn,
    const float* __restrict__ Ww, const float* __restrict__ bw,
    const float* __restrict__ Wl,
    float* __restrict__ out, int N, int numTiles)
{
    extern __shared__ float smem[];
    float* sW    = smem;                      // 128*132 tf32 bits (Wn)
    float* sA    = sW + 128 * SA_STRIDE;      // 64*132 fp32 (x_nb tile)
    float* sxs   = sA + 64 * SA_STRIDE;       // 2*128
    float* swt   = sxs + 256;                 // 2*32
    float* spart = swt + 64;                  // [wn][node][k] = 2*2*32
    float* sattn = spart + 128;               // 2*32
    float* sWw   = sattn + 64;                // 128
    float* scb   = sWw + 128;                 // 128 : bn + bw
    float* sWl   = scb + 128;                 // 128

    const int tid = threadIdx.x;
    const int w = tid >> 5, lane = tid & 31;
    const int lg = lane >> 2, lc = lane & 3;
    const int wm = w >> 1, wn = w & 1;

    // One-time loads (Wn stays resident across all tiles of this CTA)
    for (int i = tid; i < 128 * 128; i += 256) {
        int d = i >> 7, e = i & 127;
        ((uint32_t*)sW)[d * SA_STRIDE + e] = f2tf32(Wn[i]);
    }
    if (tid < 128) {
        sWw[tid] = Ww[tid];            // Ww is [D,1] contiguous
        scb[tid] = bn[tid] + bw[tid];
        sWl[tid] = Wl[tid];            // Wl is [1,D]
    }
    const uint32_t* uW = (const uint32_t*)sW;

    for (int t = blockIdx.x; t < numTiles; t += gridDim.x) {
        __syncthreads();  // protect sA/spart/sattn reuse from previous tile

        // Load x_nb tile: 64 rows x 128 floats, float4-vectorized, coalesced
        for (int i = tid; i < 64 * 32; i += 256) {
            int r = i >> 5;             // row within tile [0,64)
            int node = t * 2 + (r >> 5);
            float4 v = make_float4(0.f, 0.f, 0.f, 0.f);
            if (node < N) v = ((const float4*)x_nb)[(long)t * 2048 + i];
            *(float4*)(sA + r * SA_STRIDE + (i & 31) * 4) = v;
        }
        {   // x_s for the 2 nodes
            int node = t * 2 + (tid >> 7);
            sxs[tid] = (node < N) ? g_xs[node * 128 + (tid & 127)] : 0.f;
        }
        if (tid < 64) {
            int node = t * 2 + (tid >> 5);
            swt[tid] = (node < N) ? weight[node * 32 + (tid & 31)] : 0.f;
        }
        __syncthreads();

        // GEMM: warp tile [16 rows, 64 cols] at (wm*16, wn*64)
        float acc[8][4];
#pragma unroll
        for (int ni = 0; ni < 8; ni++)
#pragma unroll
            for (int j = 0; j < 4; j++) acc[ni][j] = 0.f;

#pragma unroll 4
        for (int ks = 0; ks < 16; ks++) {
            const int e0 = ks * 8;
            const int r = wm * 16 + lg;
            uint32_t afr[4];
            afr[0] = f2tf32(sA[r * SA_STRIDE + e0 + lc]);
            afr[1] = f2tf32(sA[(r + 8) * SA_STRIDE + e0 + lc]);
            afr[2] = f2tf32(sA[r * SA_STRIDE + e0 + 4 + lc]);
            afr[3] = f2tf32(sA[(r + 8) * SA_STRIDE + e0 + 4 + lc]);
#pragma unroll
            for (int ni = 0; ni < 8; ni++) {
                int c0 = wn * 64 + ni * 8;
                uint32_t bfr[2];
                bfr[0] = uW[(c0 + lg) * SA_STRIDE + e0 + lc];
                bfr[1] = uW[(c0 + lg) * SA_STRIDE + e0 + 4 + lc];
                mma_tf32(acc[ni], afr, bfr);
            }
        }

        // Scores: h = acc + x_s + (bn+bw) + weight*Ww ; leaky ; dot Wl
        {
            const int node = wm >> 1;
#pragma unroll
            for (int rh = 0; rh < 2; rh++) {
                int r = wm * 16 + rh * 8 + lg;   // row in [0,64)
                int k = r & 31;
                float wgt = swt[node * 32 + k];
                float p = 0.f;
#pragma unroll
                for (int ni = 0; ni < 8; ni++) {
#pragma unroll
                    for (int cc = 0; cc < 2; cc++) {
                        int d = wn * 64 + ni * 8 + 2 * lc + cc;
                        float hv = acc[ni][rh * 2 + cc] + sxs[node * 128 + d]
                                 + scb[d] + wgt * sWw[d];
                        hv = (hv >= 0.f) ? hv : 0.1f * hv;
                        p += sWl[d] * hv;
                    }
                }
                p += __shfl_xor_sync(0xffffffffu, p, 1);
                p += __shfl_xor_sync(0xffffffffu, p, 2);
                if (lc == 0) spart[(wn * 2 + node) * 32 + k] = p;  // deterministic: one writer
            }
        }
        __syncthreads();

        // Softmax over K=32 (bl dropped: softmax-invariant constant)
        if (w < 2) {
            int node = w;
            float s = spart[node * 32 + lane] + spart[(2 + node) * 32 + lane];
            float m = s;
#pragma unroll
            for (int o = 16; o; o >>= 1) m = fmaxf(m, __shfl_xor_sync(0xffffffffu, m, o));
            float e = expf(s - m);
            float sum = e;
#pragma unroll
            for (int o = 16; o; o >>= 1) sum += __shfl_xor_sync(0xffffffffu, sum, o);
            sattn[node * 32 + lane] = e / sum;
        }
        __syncthreads();

        // Output: out[n,d] = sum_k attn[k] * x_nb[n,k,d]  (x_nb from smem, fp32)
        {
            int node = tid >> 7, d = tid & 127;
            int gn = t * 2 + node;
            if (gn < N) {
                float sum = 0.f;
#pragma unroll
                for (int k = 0; k < 32; k++)
                    sum += sattn[node * 32 + k] * sA[(node * 32 + k) * SA_STRIDE + d];
                out[gn * 128 + d] = sum;
            }
        }
    }
}

// ---------------------------------------------------------------------------
extern "C" void kernel_launch(void* const* d_in, const int* in_sizes, int n_in,
                              void* d_out, int out_size)
{
    const float* x      = (const float*)d_in[0];
    const float* x_nb   = (const float*)d_in[1];
    const float* weight = (const float*)d_in[2];
    const float* Wx     = (const float*)d_in[3];
    const float* bx     = (const float*)d_in[4];
    const float* Wn     = (const float*)d_in[5];
    const float* bn     = (const float*)d_in[6];
    const float* Ww     = (const float*)d_in[7];
    const float* bw     = (const float*)d_in[8];
    const float* Wl     = (const float*)d_in[9];
    // d_in[10] = bl: constant across k -> softmax-invariant, unused.
    float* out = (float*)d_out;

    const int N = in_sizes[0] / 128;

    const size_t smem1 = (size_t)(2 * 128 * SA_STRIDE + 128) * sizeof(float);
    const size_t smem2 = (size_t)(128 * SA_STRIDE + 64 * SA_STRIDE
                                  + 256 + 64 + 128 + 64 + 128 + 128 + 128) * sizeof(float);
    cudaFuncSetAttribute(xs_kernel, cudaFuncAttributeMaxDynamicSharedMemorySize, (int)smem1);
    cudaFuncSetAttribute(gnn_main_kernel, cudaFuncAttributeMaxDynamicSharedMemorySize, (int)smem2);

    int nSM = 148;
    cudaDeviceGetAttribute(&nSM, cudaDevAttrMultiProcessorCount, 0);

    const int blocks1 = (N + 127) / 128;
    xs_kernel<<<blocks1, 256, smem1>>>(x, Wx, bx, N);

    const int numTiles = (N + 1) / 2;
    int grid = 2 * nSM;
    if (grid > numTiles) grid = numTiles;
    gnn_main_kernel<<<grid, 256, smem2>>>(x_nb, weight, Wn, bn, Ww, bw, Wl, out, N, numTiles);
}